// round 2
// baseline (speedup 1.0000x reference)
#include <cuda_runtime.h>
#include <math.h>

#define HID   1024
#define EMBD  512
#define BATCH 64
#define SEQ   512
#define G4    4096   // 4*HID
#define NBLK  128    // persistent grid size (<=148 SMs -> co-resident)

// ---------------- device scratch (no allocations allowed) ----------------
__device__ float    g_xproj[(size_t)SEQ * BATCH * G4];  // [t][b][4096]
__device__ float    g_hbuf[2][BATCH * HID];             // double-buffered h
__device__ unsigned g_count;                            // grid barrier counter

// ---------------- init ----------------
__global__ void init_kernel() {
    if (blockIdx.x == 0 && threadIdx.x == 0) g_count = 0u;
}

// ---------------- fused embedding-gather + input projection -------------
// x_proj[t][b][n] = sum_k emb_table[x[b][t]][k] * W_ih[n][k] + b_ih[n]
// grid: (4096/64, SEQ), block 256. BM=64(=B), BN=64, BK=32, micro 4x4.
__global__ void xproj_kernel(const int*   __restrict__ x,
                             const float* __restrict__ emb_table,
                             const float* __restrict__ W_ih,
                             const float* __restrict__ b_ih) {
    __shared__ float As[64][33];
    __shared__ float Bs[64][33];
    __shared__ int   toks[64];

    const int t   = blockIdx.y;
    const int n0  = blockIdx.x * 64;
    const int tid = threadIdx.x;

    if (tid < 64) toks[tid] = x[tid * SEQ + t];
    __syncthreads();

    const int ty = tid >> 4;
    const int tx = tid & 15;

    float acc[4][4];
#pragma unroll
    for (int i = 0; i < 4; i++)
#pragma unroll
        for (int j = 0; j < 4; j++) acc[i][j] = 0.0f;

    for (int kt = 0; kt < EMBD; kt += 32) {
#pragma unroll
        for (int r = 0; r < 8; r++) {
            int idx = tid + r * 256;
            int m = idx >> 5, k = idx & 31;
            int tok = toks[m];
            As[m][k] = (tok == 0) ? 0.0f : emb_table[(size_t)tok * EMBD + kt + k];
        }
#pragma unroll
        for (int r = 0; r < 8; r++) {
            int idx = tid + r * 256;
            int n = idx >> 5, k = idx & 31;
            Bs[n][k] = W_ih[(size_t)(n0 + n) * EMBD + kt + k];
        }
        __syncthreads();
#pragma unroll
        for (int k = 0; k < 32; k++) {
            float a[4], b[4];
#pragma unroll
            for (int i = 0; i < 4; i++) a[i] = As[ty * 4 + i][k];
#pragma unroll
            for (int j = 0; j < 4; j++) b[j] = Bs[tx * 4 + j][k];
#pragma unroll
            for (int i = 0; i < 4; i++)
#pragma unroll
                for (int j = 0; j < 4; j++)
                    acc[i][j] = fmaf(a[i], b[j], acc[i][j]);
        }
        __syncthreads();
    }

    float* outp = g_xproj + (size_t)t * BATCH * G4;
#pragma unroll
    for (int i = 0; i < 4; i++) {
        int lm = ty * 4 + i;
#pragma unroll
        for (int j = 0; j < 4; j++) {
            int col = n0 + tx * 4 + j;
            outp[lm * G4 + col] = acc[i][j] + b_ih[col];
        }
    }
}

// ---------------- grid barrier (monotonic counter) ----------------
__device__ __forceinline__ void grid_bar(unsigned target) {
    __syncthreads();
    if (threadIdx.x == 0) {
        __threadfence();                 // release: h writes visible
        atomicAdd(&g_count, 1u);
        while (*(volatile unsigned*)&g_count < target * NBLK) {
            __nanosleep(64);
        }
        __threadfence();                 // acquire side
    }
    __syncthreads();
}

__device__ __forceinline__ float sigmf(float v) { return 1.0f / (1.0f + expf(-v)); }

// ---------------- persistent LSTM recurrence ----------------
// Block j owns u-slice U=[8j,8j+8). It computes the 32 gate columns
// {g*1024 + 8j + ul : g in 0..3, ul in 0..7} for ALL 64 batch rows, then does
// the LSTM elementwise update for its (b,u) patch locally (c lives in regs).
// h is double-buffered in global; one grid barrier per step.
__global__ void __launch_bounds__(128, 1)
lstm_persistent(const float* __restrict__ W_hh,
                const float* __restrict__ b_hh) {
    __shared__ float As[64][33];   // h chunk [64 x 32]
    __shared__ float Bs[32][33];   // W_hh chunk [32 x 32]
    __shared__ float Gs[64][32];   // gates for this block's 32 cols
    __shared__ float bh[32];

    const int j   = blockIdx.x;        // u-slice index
    const int tid = threadIdx.x;       // 128 threads
    const int ty  = tid >> 3;          // 0..15 -> 4 batch rows each
    const int tx  = tid & 7;           // 0..7  -> 4 local cols each

    if (tid < 32) {
        int g = tid >> 3, ul = tid & 7;
        bh[tid] = b_hh[g * HID + j * 8 + ul];
    }

    // zero own h slice in buffer 0; c kept in registers
    float creg[4];
#pragma unroll
    for (int q = 0; q < 4; q++) {
        creg[q] = 0.0f;
        int e = tid + 128 * q;                 // 0..511
        int b = e >> 3, ul = e & 7;
        g_hbuf[0][b * HID + j * 8 + ul] = 0.0f;
    }
    unsigned barnum = 0;
    grid_bar(++barnum);

    for (int t = 0; t < SEQ; t++) {
        const int cb = t & 1, nb = cb ^ 1;

        // prefetch this thread's x_proj values (consumed in epilogue)
        float xpr[16];
        const float* xp = g_xproj + (size_t)t * BATCH * G4;
#pragma unroll
        for (int i = 0; i < 4; i++) {
            int m = ty * 4 + i;
#pragma unroll
            for (int j2 = 0; j2 < 4; j2++) {
                int nl = tx * 4 + j2;
                int n  = (nl >> 3) * HID + j * 8 + (nl & 7);
                xpr[i * 4 + j2] = __ldcs(xp + m * G4 + n);
            }
        }

        float acc[4][4];
#pragma unroll
        for (int i = 0; i < 4; i++)
#pragma unroll
            for (int j2 = 0; j2 < 4; j2++) acc[i][j2] = 0.0f;

        const float* hsrc = g_hbuf[cb];
        for (int kt = 0; kt < HID; kt += 32) {
#pragma unroll
            for (int r = 0; r < 16; r++) {             // As: 64x32 of h (L2-fresh)
                int idx = tid + r * 128;
                int m = idx >> 5, k = idx & 31;
                As[m][k] = __ldcg(hsrc + m * HID + kt + k);
            }
#pragma unroll
            for (int r = 0; r < 8; r++) {              // Bs: 32x32 of W_hh slice
                int idx = tid + r * 128;
                int nl = idx >> 5, k = idx & 31;
                int n  = (nl >> 3) * HID + j * 8 + (nl & 7);
                Bs[nl][k] = W_hh[(size_t)n * HID + kt + k];
            }
            __syncthreads();
#pragma unroll
            for (int k = 0; k < 32; k++) {
                float a[4], b[4];
#pragma unroll
                for (int i = 0; i < 4; i++) a[i] = As[ty * 4 + i][k];
#pragma unroll
                for (int j2 = 0; j2 < 4; j2++) b[j2] = Bs[tx * 4 + j2][k];
#pragma unroll
                for (int i = 0; i < 4; i++)
#pragma unroll
                    for (int j2 = 0; j2 < 4; j2++)
                        acc[i][j2] = fmaf(a[i], b[j2], acc[i][j2]);
            }
            __syncthreads();
        }

        // epilogue: gates -> smem
#pragma unroll
        for (int i = 0; i < 4; i++) {
            int m = ty * 4 + i;
#pragma unroll
            for (int j2 = 0; j2 < 4; j2++) {
                int nl = tx * 4 + j2;
                Gs[m][nl] = acc[i][j2] + xpr[i * 4 + j2] + bh[nl];
            }
        }
        __syncthreads();

        // LSTM elementwise update (block-local)
#pragma unroll
        for (int q = 0; q < 4; q++) {
            int e = tid + 128 * q;
            int b = e >> 3, ul = e & 7;
            float ig = Gs[b][ul];
            float fg = Gs[b][8 + ul];
            float gg = Gs[b][16 + ul];
            float og = Gs[b][24 + ul];
            float cn = sigmf(fg) * creg[q] + sigmf(ig) * tanhf(gg);
            creg[q] = cn;
            g_hbuf[nb][b * HID + j * 8 + ul] = sigmf(og) * tanhf(cn);
        }
        grid_bar(++barnum);    // includes __syncthreads + release fence
    }
}

// ---------------- head: relu(h@W1^T+b1) @ W2^T + b2 ----------------
__global__ void final_kernel(const float* __restrict__ W1,
                             const float* __restrict__ b1,
                             const float* __restrict__ W2,
                             const float* __restrict__ b2,
                             float* __restrict__ out) {
    __shared__ float red[64];
    int b = blockIdx.x;
    int jj = threadIdx.x;
    const float* hrow = g_hbuf[SEQ & 1] + b * HID;   // SEQ even -> buffer 0
    const float* wrow = W1 + jj * HID;
    float s = 0.0f;
    for (int k = 0; k < HID; k++) s = fmaf(hrow[k], wrow[k], s);
    float hid = fmaxf(s + b1[jj], 0.0f);
    red[jj] = hid * W2[jj];
    __syncthreads();
    if (jj == 0) {
        float o = b2[0];
#pragma unroll
        for (int q = 0; q < 64; q++) o += red[q];
        out[b] = o;
    }
}

// ---------------- launch (4 graph nodes total) ----------------
extern "C" void kernel_launch(void* const* d_in, const int* in_sizes, int n_in,
                              void* d_out, int out_size) {
    (void)in_sizes; (void)n_in; (void)out_size;
    const int*   x         = (const int*)  d_in[0];
    // d_in[1] = lengths : unused by the reference computation
    const float* emb_table = (const float*)d_in[2];
    const float* W_ih      = (const float*)d_in[3];
    const float* b_ih      = (const float*)d_in[4];
    const float* W_hh      = (const float*)d_in[5];
    const float* b_hh      = (const float*)d_in[6];
    const float* W1        = (const float*)d_in[7];
    const float* b1        = (const float*)d_in[8];
    const float* W2        = (const float*)d_in[9];
    const float* b2        = (const float*)d_in[10];
    float* out = (float*)d_out;

    init_kernel<<<1, 32>>>();
    xproj_kernel<<<dim3(G4 / 64, SEQ), 256>>>(x, emb_table, W_ih, b_ih);
    lstm_persistent<<<NBLK, 128>>>(W_hh, b_hh);
    final_kernel<<<BATCH, 64>>>(W1, b1, W2, b2, out);
}

// round 4
// speedup vs baseline: 1.6838x; 1.6838x over previous
#include <cuda_runtime.h>
#include <cuda_bf16.h>
#include <math.h>
#include <stdint.h>

#define HID   1024
#define EMBD  512
#define BATCH 64
#define SEQ   512
#define G4    4096
#define NBLK  128
#define NTHR  128

// ===================== device scratch =====================
__device__ float    g_xproj[(size_t)SEQ * BATCH * G4];     // [t][b][4096]
// W_hh in m16n8k16 B-fragment order, bf16 hi/lo:
//   u32 idx = (((jj*64 + s)*4 + g)*32 + lane)*4 + part*2 + khalf
__device__ uint32_t g_wfrag[128 * 64 * 4 * 32 * 4];        // 16 MB
// h in A-fragment order, bf16 hi/lo, double buffered:
//   u32 idx = ((s*4 + mt)*32 + lane)*8 + part*4 + reg,  reg=(khalf<<1)|mhalf
__device__ uint32_t g_hfrag[2][64 * 4 * 32 * 8];           // 512 KB x2
__device__ float    g_hfin[BATCH * HID];                    // final h, fp32
__device__ unsigned g_count;

__global__ void init_kernel() {
    if (blockIdx.x == 0 && threadIdx.x == 0) g_count = 0u;
}

// ===================== helpers =====================
__device__ __forceinline__ float sigmf(float v) { return 1.0f / (1.0f + expf(-v)); }

__device__ __forceinline__ uint32_t pack_bf16x2(float e0, float e1) {
    // e0 -> low half (k even), e1 -> high half
    uint16_t u0 = __bfloat16_as_ushort(__float2bfloat16(e0));
    uint16_t u1 = __bfloat16_as_ushort(__float2bfloat16(e1));
    return (uint32_t)u0 | ((uint32_t)u1 << 16);
}

#define MMA_BF16(d, a, b0, b1) \
    asm volatile("mma.sync.aligned.m16n8k16.row.col.f32.bf16.bf16.f32 " \
        "{%0,%1,%2,%3}, {%4,%5,%6,%7}, {%8,%9}, {%0,%1,%2,%3};" \
        : "+f"((d)[0]), "+f"((d)[1]), "+f"((d)[2]), "+f"((d)[3]) \
        : "r"((a).x), "r"((a).y), "r"((a).z), "r"((a).w), "r"(b0), "r"(b1))

// ===================== W_hh -> fragment converter =====================
// one thread per bf16x2 pair of W_hh (n, k even)
__global__ void wconv_kernel(const float* __restrict__ W_hh) {
    int id = blockIdx.x * blockDim.x + threadIdx.x;   // 4096*512
    if (id >= 4096 * 512) return;
    int n  = id >> 9;
    int k  = (id & 511) * 2;
    float2 w = *(const float2*)(W_hh + (size_t)n * HID + k);
    float hi0 = __bfloat162float(__float2bfloat16(w.x));
    float hi1 = __bfloat162float(__float2bfloat16(w.y));
    uint32_t ph = pack_bf16x2(w.x, w.y);
    uint32_t pl = pack_bf16x2(w.x - hi0, w.y - hi1);

    int g  = n >> 10, jj = (n >> 3) & 127, ul = n & 7;
    int s  = k >> 4, tig = (k >> 1) & 3, khalf = (k >> 3) & 1;
    int lane = (ul << 2) | tig;
    uint32_t base = (uint32_t)((((jj * 64 + s) * 4 + g) * 32 + lane) * 4);
    g_wfrag[base + khalf]     = ph;   // part 0 (hi)
    g_wfrag[base + 2 + khalf] = pl;   // part 1 (lo)
}

// ===================== fused gather + input projection (unchanged) =====================
__global__ void xproj_kernel(const int*   __restrict__ x,
                             const float* __restrict__ emb_table,
                             const float* __restrict__ W_ih,
                             const float* __restrict__ b_ih) {
    __shared__ float As[64][33];
    __shared__ float Bs[64][33];
    __shared__ int   toks[64];

    const int t   = blockIdx.y;
    const int n0  = blockIdx.x * 64;
    const int tid = threadIdx.x;

    if (tid < 64) toks[tid] = x[tid * SEQ + t];
    __syncthreads();

    const int ty = tid >> 4;
    const int tx = tid & 15;

    float acc[4][4];
#pragma unroll
    for (int i = 0; i < 4; i++)
#pragma unroll
        for (int j = 0; j < 4; j++) acc[i][j] = 0.0f;

    for (int kt = 0; kt < EMBD; kt += 32) {
#pragma unroll
        for (int r = 0; r < 8; r++) {
            int idx = tid + r * 256;
            int m = idx >> 5, k = idx & 31;
            int tok = toks[m];
            As[m][k] = (tok == 0) ? 0.0f : emb_table[(size_t)tok * EMBD + kt + k];
        }
#pragma unroll
        for (int r = 0; r < 8; r++) {
            int idx = tid + r * 256;
            int n = idx >> 5, k = idx & 31;
            Bs[n][k] = W_ih[(size_t)(n0 + n) * EMBD + kt + k];
        }
        __syncthreads();
#pragma unroll
        for (int k = 0; k < 32; k++) {
            float a[4], b[4];
#pragma unroll
            for (int i = 0; i < 4; i++) a[i] = As[ty * 4 + i][k];
#pragma unroll
            for (int j = 0; j < 4; j++) b[j] = Bs[tx * 4 + j][k];
#pragma unroll
            for (int i = 0; i < 4; i++)
#pragma unroll
                for (int j = 0; j < 4; j++)
                    acc[i][j] = fmaf(a[i], b[j], acc[i][j]);
        }
        __syncthreads();
    }

    float* outp = g_xproj + (size_t)t * BATCH * G4;
#pragma unroll
    for (int i = 0; i < 4; i++) {
        int lm = ty * 4 + i;
#pragma unroll
        for (int j = 0; j < 4; j++) {
            int col = n0 + tx * 4 + j;
            outp[lm * G4 + col] = acc[i][j] + b_ih[col];
        }
    }
}

// ===================== grid barrier =====================
__device__ __forceinline__ void grid_bar(unsigned target) {
    __syncthreads();
    if (threadIdx.x == 0) {
        __threadfence();
        atomicAdd(&g_count, 1u);
        while (*(volatile unsigned*)&g_count < target * NBLK) {
            __nanosleep(64);
        }
        __threadfence();
    }
    __syncthreads();
}

// ===================== persistent LSTM recurrence (HMMA) =====================
// Block j owns gate columns {g*1024 + j*8 + ul}. Warp w = m-tile w (rows 16w..16w+15).
// Each warp: D[16 x 32] = h[16 x 1024] . Wslice^T via m16n8k16 bf16 mma, hi/lo split.
__global__ void __launch_bounds__(NTHR, 1)
lstm_persistent(const float* __restrict__ b_hh) {
    __shared__ float xs[64][36];
    __shared__ float bhs[32];

    const int j   = blockIdx.x;
    const int tid = threadIdx.x;
    const int wid = tid >> 5;
    const int lid = tid & 31;
    const int r0  = wid * 16 + (lid >> 2);   // lane's base row (batch)
    const int tig = lid & 3;
    const int sj  = j >> 1;                  // h-frag k-step this block writes
    const int regbase = (j & 1) << 1;        // khalf bit of written reg

    if (tid < 32) {
        int g = tid >> 3, ul = tid & 7;
        bhs[tid] = b_hh[g * HID + j * 8 + ul];
    }

    // zero-init h buffer 0 via this block's own fragment slots
    {
        uint32_t* hb = g_hfrag[0] + (((sj * 4 + wid) * 32 + lid) * 8);
#pragma unroll
        for (int mh = 0; mh < 2; mh++) {
            hb[regbase + mh]     = 0u;
            hb[4 + regbase + mh] = 0u;
        }
    }
    float creg[4];   // c for (mh, colbit)
#pragma unroll
    for (int q = 0; q < 4; q++) creg[q] = 0.0f;

    unsigned barnum = 0;
    grid_bar(++barnum);

    const uint4* wbase = ((const uint4*)g_wfrag) + (size_t)j * (64 * 4 * 32) + lid;

    for (int t = 0; t < SEQ; t++) {
        const int cb = t & 1, nb = cb ^ 1;

        // ---- prestage x_proj tile [64 b x 32 cols] into smem (consumed post-loop)
        {
            int b = tid >> 1;
            int g0 = (tid & 1) * 2;
            const float* xp = g_xproj + (size_t)t * BATCH * G4 + (size_t)b * G4 + j * 8;
#pragma unroll
            for (int gg = 0; gg < 2; gg++) {
                int g = g0 + gg;
                float4 v0 = __ldcs((const float4*)(xp + g * HID));
                float4 v1 = __ldcs((const float4*)(xp + g * HID) + 1);
                *(float4*)&xs[b][g * 8]     = v0;
                *(float4*)&xs[b][g * 8 + 4] = v1;
            }
        }

        // ---- K loop: 64 k-steps of m16n8k16, hi/lo split (3 mma per g)
        const uint4* habase = ((const uint4*)g_hfrag[cb]) + wid * 64 + lid * 2;
        // uint4 idx of A frag (s, mt=wid, lane, part): ((s*4+wid)*32+lid)*2 + part
        uint4 Ab[2][4][2];
        uint4 Bb[2][4];
        float acc[4][4];
#pragma unroll
        for (int g = 0; g < 4; g++)
#pragma unroll
            for (int c = 0; c < 4; c++) acc[g][c] = 0.0f;

#pragma unroll
        for (int u = 0; u < 4; u++) {
            const uint4* p = habase + (size_t)u * 256;   // s stride = 4*32*2 uint4
            Ab[0][u][0] = __ldcg(p);
            Ab[0][u][1] = __ldcg(p + 1);
        }
#pragma unroll
        for (int g = 0; g < 4; g++) Bb[0][g] = __ldg(wbase + g * 32);

#pragma unroll 8
        for (int s = 0; s < 64; s++) {
            const int u  = s & 3;
            const int ab = (s >> 2) & 1;
            const int bb = s & 1;
            if (s < 63) {
                const uint4* wp = wbase + (size_t)(s + 1) * 128;
#pragma unroll
                for (int g = 0; g < 4; g++) Bb[bb ^ 1][g] = __ldg(wp + g * 32);
            }
            if (s < 60) {
                const uint4* p = habase + (size_t)(s + 4) * 256;
                Ab[ab ^ 1][u][0] = __ldcg(p);
                Ab[ab ^ 1][u][1] = __ldcg(p + 1);
            }
            uint4 A0 = Ab[ab][u][0];
            uint4 A1 = Ab[ab][u][1];
#pragma unroll
            for (int g = 0; g < 4; g++) {
                uint4 B = Bb[bb][g];
                MMA_BF16(acc[g], A0, B.x, B.y);   // hi(A).hi(W)
                MMA_BF16(acc[g], A0, B.z, B.w);   // hi(A).lo(W)
                MMA_BF16(acc[g], A1, B.x, B.y);   // lo(A).hi(W)
            }
        }

        __syncthreads();   // xs staged by all threads -> readable

        // ---- LSTM update: lane holds all 4 gates for (r0,2tig..+1) and (r0+8,...)
        uint32_t* hb = g_hfrag[nb] + (((sj * 4 + wid) * 32 + lid) * 8);
#pragma unroll
        for (int mh = 0; mh < 2; mh++) {
            int row = r0 + 8 * mh;
            float h2[2];
#pragma unroll
            for (int cbit = 0; cbit < 2; cbit++) {
                int ci = mh * 2 + cbit;
                int ul = 2 * tig + cbit;
                float ig = acc[0][ci] + xs[row][ul]      + bhs[ul];
                float fg = acc[1][ci] + xs[row][8 + ul]  + bhs[8 + ul];
                float gg = acc[2][ci] + xs[row][16 + ul] + bhs[16 + ul];
                float og = acc[3][ci] + xs[row][24 + ul] + bhs[24 + ul];
                float cn = sigmf(fg) * creg[ci] + sigmf(ig) * tanhf(gg);
                creg[ci] = cn;
                h2[cbit] = sigmf(og) * tanhf(cn);
            }
            float hi0 = __bfloat162float(__float2bfloat16(h2[0]));
            float hi1 = __bfloat162float(__float2bfloat16(h2[1]));
            hb[regbase + mh]     = pack_bf16x2(h2[0], h2[1]);
            hb[4 + regbase + mh] = pack_bf16x2(h2[0] - hi0, h2[1] - hi1);
            if (t == SEQ - 1) {
                *(float2*)(g_hfin + row * HID + j * 8 + 2 * tig) =
                    make_float2(h2[0], h2[1]);
            }
        }
        grid_bar(++barnum);
    }
}

// ===================== head =====================
__global__ void final_kernel(const float* __restrict__ W1,
                             const float* __restrict__ b1,
                             const float* __restrict__ W2,
                             const float* __restrict__ b2,
                             float* __restrict__ out) {
    __shared__ float red[64];
    int b = blockIdx.x;
    int jj = threadIdx.x;
    const float* hrow = g_hfin + b * HID;
    const float* wrow = W1 + jj * HID;
    float s = 0.0f;
    for (int k = 0; k < HID; k++) s = fmaf(hrow[k], wrow[k], s);
    float hid = fmaxf(s + b1[jj], 0.0f);
    red[jj] = hid * W2[jj];
    __syncthreads();
    if (jj == 0) {
        float o = b2[0];
#pragma unroll
        for (int q = 0; q < 64; q++) o += red[q];
        out[b] = o;
    }
}

// ===================== launch =====================
extern "C" void kernel_launch(void* const* d_in, const int* in_sizes, int n_in,
                              void* d_out, int out_size) {
    (void)in_sizes; (void)n_in; (void)out_size;
    const int*   x         = (const int*)  d_in[0];
    const float* emb_table = (const float*)d_in[2];
    const float* W_ih      = (const float*)d_in[3];
    const float* b_ih      = (const float*)d_in[4];
    const float* W_hh      = (const float*)d_in[5];
    const float* b_hh      = (const float*)d_in[6];
    const float* W1        = (const float*)d_in[7];
    const float* b1        = (const float*)d_in[8];
    const float* W2        = (const float*)d_in[9];
    const float* b2        = (const float*)d_in[10];
    float* out = (float*)d_out;

    init_kernel<<<1, 32>>>();
    wconv_kernel<<<(4096 * 512 + 255) / 256, 256>>>(W_hh);
    xproj_kernel<<<dim3(G4 / 64, SEQ), 256>>>(x, emb_table, W_ih, b_ih);
    lstm_persistent<<<NBLK, NTHR>>>(b_hh);
    final_kernel<<<BATCH, 64>>>(W1, b1, W2, b2, out);
}

// round 5
// speedup vs baseline: 3.0366x; 1.8034x over previous
#include <cuda_runtime.h>
#include <cuda_bf16.h>
#include <math.h>
#include <stdint.h>

#define HID   1024
#define EMBD  512
#define BATCH 64
#define SEQ   512
#define G4    4096
#define NBLK  128
#define NTHR  128

// ===================== device scratch =====================
__device__ float    g_xproj[(size_t)SEQ * BATCH * G4];     // [t][b][4096] == [m][4096], m=t*64+b
// W_hh in m16n8k16 B-fragment order, bf16 hi/lo (recurrence):
//   u32 idx = (((jj*64 + s)*4 + g)*32 + lane)*4 + part*2 + khalf
__device__ uint32_t g_wfrag[128 * 64 * 4 * 32 * 4];        // 16 MB
// W_ih in B-fragment order, bf16 hi/lo (xproj):
//   u32 idx = ((ntile*32 + s)*32 + lane)*4 + part*2 + khalf   (ntile: 512, s: 32)
__device__ uint32_t g_wihfrag[512 * 32 * 32 * 4];          // 8 MB
// emb rows (m=t*64+b, k=0..511) in A-fragment order, bf16 hi/lo:
//   uint4 idx = ((mtile*32 + s)*32 + lane)*2 + part        (mtile: 2048, s: 32)
__device__ uint4    g_afrag[2048 * 32 * 32 * 2];           // 67 MB
// h in A-fragment order, bf16 hi/lo, double buffered:
__device__ uint32_t g_hfrag[2][64 * 4 * 32 * 8];           // 512 KB x2
__device__ float    g_hfin[BATCH * HID];
__device__ unsigned g_count;

__global__ void init_kernel() {
    if (blockIdx.x == 0 && threadIdx.x == 0) g_count = 0u;
}

// ===================== helpers =====================
__device__ __forceinline__ float sigmf(float v) { return 1.0f / (1.0f + expf(-v)); }

__device__ __forceinline__ uint32_t pack_bf16x2(float e0, float e1) {
    uint16_t u0 = __bfloat16_as_ushort(__float2bfloat16(e0));
    uint16_t u1 = __bfloat16_as_ushort(__float2bfloat16(e1));
    return (uint32_t)u0 | ((uint32_t)u1 << 16);
}

#define MMA_BF16(d, a, b0, b1) \
    asm volatile("mma.sync.aligned.m16n8k16.row.col.f32.bf16.bf16.f32 " \
        "{%0,%1,%2,%3}, {%4,%5,%6,%7}, {%8,%9}, {%0,%1,%2,%3};" \
        : "+f"((d)[0]), "+f"((d)[1]), "+f"((d)[2]), "+f"((d)[3]) \
        : "r"((a).x), "r"((a).y), "r"((a).z), "r"((a).w), "r"(b0), "r"(b1))

// ===================== W_hh -> fragment converter (unchanged) =====================
__global__ void wconv_kernel(const float* __restrict__ W_hh) {
    int id = blockIdx.x * blockDim.x + threadIdx.x;   // 4096*512
    if (id >= 4096 * 512) return;
    int n  = id >> 9;
    int k  = (id & 511) * 2;
    float2 w = *(const float2*)(W_hh + (size_t)n * HID + k);
    float hi0 = __bfloat162float(__float2bfloat16(w.x));
    float hi1 = __bfloat162float(__float2bfloat16(w.y));
    uint32_t ph = pack_bf16x2(w.x, w.y);
    uint32_t pl = pack_bf16x2(w.x - hi0, w.y - hi1);

    int g  = n >> 10, jj = (n >> 3) & 127, ul = n & 7;
    int s  = k >> 4, tig = (k >> 1) & 3, khalf = (k >> 3) & 1;
    int lane = (ul << 2) | tig;
    uint32_t base = (uint32_t)((((jj * 64 + s) * 4 + g) * 32 + lane) * 4);
    g_wfrag[base + khalf]     = ph;
    g_wfrag[base + 2 + khalf] = pl;
}

// ===================== W_ih -> fragment converter =====================
__global__ void wihconv_kernel(const float* __restrict__ W_ih) {
    int id = blockIdx.x * blockDim.x + threadIdx.x;   // 4096*256 k-pairs
    if (id >= 4096 * 256) return;
    int n  = id >> 8;
    int k  = (id & 255) * 2;
    float2 w = *(const float2*)(W_ih + (size_t)n * EMBD + k);
    float hi0 = __bfloat162float(__float2bfloat16(w.x));
    float hi1 = __bfloat162float(__float2bfloat16(w.y));
    uint32_t ph = pack_bf16x2(w.x, w.y);
    uint32_t pl = pack_bf16x2(w.x - hi0, w.y - hi1);

    int ntile = n >> 3, ul = n & 7;
    int s = k >> 4, tig = (k >> 1) & 3, khalf = (k >> 3) & 1;
    int lane = (ul << 2) | tig;
    uint32_t base = (uint32_t)(((ntile * 32 + s) * 32 + lane) * 4);
    g_wihfrag[base + khalf]     = ph;
    g_wihfrag[base + 2 + khalf] = pl;
}

// ===================== embedding gather -> A fragments =====================
// block = one mtile (16 rows of m=t*64+b); 8 warps x 4 ksteps each.
__global__ void gather_kernel(const int*   __restrict__ x,
                              const float* __restrict__ emb_table) {
    __shared__ int toks[16];
    const int mtile = blockIdx.x;
    const int tid = threadIdx.x;
    const int wid = tid >> 5;
    const int lid = tid & 31;

    if (tid < 16) {
        int m = mtile * 16 + tid;
        int t = m >> 6, b = m & 63;
        toks[tid] = x[b * SEQ + t];
    }
    __syncthreads();

    const int r0 = lid >> 2;
    const int c0 = (lid & 3) * 2;
    const int tok0 = toks[r0];
    const int tok1 = toks[r0 + 8];
    const float* e0 = emb_table + (size_t)tok0 * EMBD;
    const float* e1 = emb_table + (size_t)tok1 * EMBD;

#pragma unroll
    for (int q = 0; q < 4; q++) {
        int s = wid * 4 + q;
        int kb = s * 16;
        float2 v00 = (tok0 == 0) ? make_float2(0.f, 0.f) : *(const float2*)(e0 + kb + c0);
        float2 v01 = (tok0 == 0) ? make_float2(0.f, 0.f) : *(const float2*)(e0 + kb + c0 + 8);
        float2 v10 = (tok1 == 0) ? make_float2(0.f, 0.f) : *(const float2*)(e1 + kb + c0);
        float2 v11 = (tok1 == 0) ? make_float2(0.f, 0.f) : *(const float2*)(e1 + kb + c0 + 8);

        uint4 hi, lo;
        // reg = (khalf<<1)|mhalf : x=(kh0,row0) y=(kh0,row1) z=(kh1,row0) w=(kh1,row1)
        hi.x = pack_bf16x2(v00.x, v00.y);
        hi.y = pack_bf16x2(v10.x, v10.y);
        hi.z = pack_bf16x2(v01.x, v01.y);
        hi.w = pack_bf16x2(v11.x, v11.y);
        lo.x = pack_bf16x2(v00.x - __bfloat162float(__float2bfloat16(v00.x)),
                           v00.y - __bfloat162float(__float2bfloat16(v00.y)));
        lo.y = pack_bf16x2(v10.x - __bfloat162float(__float2bfloat16(v10.x)),
                           v10.y - __bfloat162float(__float2bfloat16(v10.y)));
        lo.z = pack_bf16x2(v01.x - __bfloat162float(__float2bfloat16(v01.x)),
                           v01.y - __bfloat162float(__float2bfloat16(v01.y)));
        lo.w = pack_bf16x2(v11.x - __bfloat162float(__float2bfloat16(v11.x)),
                           v11.y - __bfloat162float(__float2bfloat16(v11.y)));

        uint4* dst = g_afrag + (((size_t)mtile * 32 + s) * 32 + lid) * 2;
        dst[0] = hi;
        dst[1] = lo;
    }
}

// ===================== xproj GEMM (HMMA, hi/lo split) =====================
// M=32768 (t*64+b), N=4096, K=512. grid (256, 32), 8 warps.
// warp: mtile = bx*8+wid (16 rows), 16 n8-frags (128 cols), 32 ksteps.
__global__ void __launch_bounds__(256, 1)
xproj_mma(const float* __restrict__ b_ih) {
    const int tid = threadIdx.x;
    const int wid = tid >> 5;
    const int lid = tid & 31;
    const int mtile = blockIdx.x * 8 + wid;
    const int nt0   = blockIdx.y * 16;

    float acc[16][4];
#pragma unroll
    for (int nf = 0; nf < 16; nf++)
#pragma unroll
        for (int c = 0; c < 4; c++) acc[nf][c] = 0.0f;

    const uint4* abase = g_afrag + ((size_t)mtile * 32) * 32 * 2 + lid * 2;
    const uint4* bbase = ((const uint4*)g_wihfrag) + ((size_t)nt0 * 32) * 32 + lid;

    for (int s = 0; s < 32; s++) {
        uint4 Ah = __ldcg(abase + (size_t)s * 64);
        uint4 Al = __ldcg(abase + (size_t)s * 64 + 1);
        const uint4* bp = bbase + (size_t)s * 32;
#pragma unroll
        for (int nf = 0; nf < 16; nf++) {
            uint4 B = __ldg(bp + (size_t)nf * 32 * 32);   // (hi kh0, hi kh1, lo kh0, lo kh1)
            MMA_BF16(acc[nf], Ah, B.x, B.y);
            MMA_BF16(acc[nf], Ah, B.z, B.w);
            MMA_BF16(acc[nf], Al, B.x, B.y);
        }
    }

    // epilogue: D-frag -> g_xproj[m][col] + b_ih
    const int row0 = mtile * 16 + (lid >> 2);
    const int cbase = (lid & 3) * 2;
    float* o0 = g_xproj + (size_t)row0 * G4;
    float* o1 = g_xproj + (size_t)(row0 + 8) * G4;
#pragma unroll
    for (int nf = 0; nf < 16; nf++) {
        int col = (nt0 + nf) * 8 + cbase;
        float2 bias = *(const float2*)(b_ih + col);
        *(float2*)(o0 + col) = make_float2(acc[nf][0] + bias.x, acc[nf][1] + bias.y);
        *(float2*)(o1 + col) = make_float2(acc[nf][2] + bias.x, acc[nf][3] + bias.y);
    }
}

// ===================== grid barrier =====================
__device__ __forceinline__ void grid_bar(unsigned target) {
    __syncthreads();
    if (threadIdx.x == 0) {
        __threadfence();
        atomicAdd(&g_count, 1u);
        while (*(volatile unsigned*)&g_count < target * NBLK) {
            __nanosleep(64);
        }
        __threadfence();
    }
    __syncthreads();
}

// ===================== persistent LSTM recurrence (HMMA) — unchanged =====================
__global__ void __launch_bounds__(NTHR, 1)
lstm_persistent(const float* __restrict__ b_hh) {
    __shared__ float xs[64][36];
    __shared__ float bhs[32];

    const int j   = blockIdx.x;
    const int tid = threadIdx.x;
    const int wid = tid >> 5;
    const int lid = tid & 31;
    const int r0  = wid * 16 + (lid >> 2);
    const int tig = lid & 3;
    const int sj  = j >> 1;
    const int regbase = (j & 1) << 1;

    if (tid < 32) {
        int g = tid >> 3, ul = tid & 7;
        bhs[tid] = b_hh[g * HID + j * 8 + ul];
    }

    {
        uint32_t* hb = g_hfrag[0] + (((sj * 4 + wid) * 32 + lid) * 8);
#pragma unroll
        for (int mh = 0; mh < 2; mh++) {
            hb[regbase + mh]     = 0u;
            hb[4 + regbase + mh] = 0u;
        }
    }
    float creg[4];
#pragma unroll
    for (int q = 0; q < 4; q++) creg[q] = 0.0f;

    unsigned barnum = 0;
    grid_bar(++barnum);

    const uint4* wbase = ((const uint4*)g_wfrag) + (size_t)j * (64 * 4 * 32) + lid;

    for (int t = 0; t < SEQ; t++) {
        const int cb = t & 1, nb = cb ^ 1;

        {
            int b = tid >> 1;
            int g0 = (tid & 1) * 2;
            const float* xp = g_xproj + (size_t)t * BATCH * G4 + (size_t)b * G4 + j * 8;
#pragma unroll
            for (int gg = 0; gg < 2; gg++) {
                int g = g0 + gg;
                float4 v0 = __ldcs((const float4*)(xp + g * HID));
                float4 v1 = __ldcs((const float4*)(xp + g * HID) + 1);
                *(float4*)&xs[b][g * 8]     = v0;
                *(float4*)&xs[b][g * 8 + 4] = v1;
            }
        }

        const uint4* habase = ((const uint4*)g_hfrag[cb]) + wid * 64 + lid * 2;
        uint4 Ab[2][4][2];
        uint4 Bb[2][4];
        float acc[4][4];
#pragma unroll
        for (int g = 0; g < 4; g++)
#pragma unroll
            for (int c = 0; c < 4; c++) acc[g][c] = 0.0f;

#pragma unroll
        for (int u = 0; u < 4; u++) {
            const uint4* p = habase + (size_t)u * 256;
            Ab[0][u][0] = __ldcg(p);
            Ab[0][u][1] = __ldcg(p + 1);
        }
#pragma unroll
        for (int g = 0; g < 4; g++) Bb[0][g] = __ldg(wbase + g * 32);

#pragma unroll 8
        for (int s = 0; s < 64; s++) {
            const int u  = s & 3;
            const int ab = (s >> 2) & 1;
            const int bb = s & 1;
            if (s < 63) {
                const uint4* wp = wbase + (size_t)(s + 1) * 128;
#pragma unroll
                for (int g = 0; g < 4; g++) Bb[bb ^ 1][g] = __ldg(wp + g * 32);
            }
            if (s < 60) {
                const uint4* p = habase + (size_t)(s + 4) * 256;
                Ab[ab ^ 1][u][0] = __ldcg(p);
                Ab[ab ^ 1][u][1] = __ldcg(p + 1);
            }
            uint4 A0 = Ab[ab][u][0];
            uint4 A1 = Ab[ab][u][1];
#pragma unroll
            for (int g = 0; g < 4; g++) {
                uint4 B = Bb[bb][g];
                MMA_BF16(acc[g], A0, B.x, B.y);
                MMA_BF16(acc[g], A0, B.z, B.w);
                MMA_BF16(acc[g], A1, B.x, B.y);
            }
        }

        __syncthreads();

        uint32_t* hb = g_hfrag[nb] + (((sj * 4 + wid) * 32 + lid) * 8);
#pragma unroll
        for (int mh = 0; mh < 2; mh++) {
            int row = r0 + 8 * mh;
            float h2[2];
#pragma unroll
            for (int cbit = 0; cbit < 2; cbit++) {
                int ci = mh * 2 + cbit;
                int ul = 2 * tig + cbit;
                float ig = acc[0][ci] + xs[row][ul]      + bhs[ul];
                float fg = acc[1][ci] + xs[row][8 + ul]  + bhs[8 + ul];
                float gg = acc[2][ci] + xs[row][16 + ul] + bhs[16 + ul];
                float og = acc[3][ci] + xs[row][24 + ul] + bhs[24 + ul];
                float cn = sigmf(fg) * creg[ci] + sigmf(ig) * tanhf(gg);
                creg[ci] = cn;
                h2[cbit] = sigmf(og) * tanhf(cn);
            }
            float hi0 = __bfloat162float(__float2bfloat16(h2[0]));
            float hi1 = __bfloat162float(__float2bfloat16(h2[1]));
            hb[regbase + mh]     = pack_bf16x2(h2[0], h2[1]);
            hb[4 + regbase + mh] = pack_bf16x2(h2[0] - hi0, h2[1] - hi1);
            if (t == SEQ - 1) {
                *(float2*)(g_hfin + row * HID + j * 8 + 2 * tig) =
                    make_float2(h2[0], h2[1]);
            }
        }
        grid_bar(++barnum);
    }
}

// ===================== head (unchanged) =====================
__global__ void final_kernel(const float* __restrict__ W1,
                             const float* __restrict__ b1,
                             const float* __restrict__ W2,
                             const float* __restrict__ b2,
                             float* __restrict__ out) {
    __shared__ float red[64];
    int b = blockIdx.x;
    int jj = threadIdx.x;
    const float* hrow = g_hfin + b * HID;
    const float* wrow = W1 + jj * HID;
    float s = 0.0f;
    for (int k = 0; k < HID; k++) s = fmaf(hrow[k], wrow[k], s);
    float hid = fmaxf(s + b1[jj], 0.0f);
    red[jj] = hid * W2[jj];
    __syncthreads();
    if (jj == 0) {
        float o = b2[0];
#pragma unroll
        for (int q = 0; q < 64; q++) o += red[q];
        out[b] = o;
    }
}

// ===================== launch =====================
extern "C" void kernel_launch(void* const* d_in, const int* in_sizes, int n_in,
                              void* d_out, int out_size) {
    (void)in_sizes; (void)n_in; (void)out_size;
    const int*   x         = (const int*)  d_in[0];
    const float* emb_table = (const float*)d_in[2];
    const float* W_ih      = (const float*)d_in[3];
    const float* b_ih      = (const float*)d_in[4];
    const float* W_hh      = (const float*)d_in[5];
    const float* b_hh      = (const float*)d_in[6];
    const float* W1        = (const float*)d_in[7];
    const float* b1        = (const float*)d_in[8];
    const float* W2        = (const float*)d_in[9];
    const float* b2        = (const float*)d_in[10];
    float* out = (float*)d_out;

    init_kernel<<<1, 32>>>();
    wconv_kernel<<<(4096 * 512 + 255) / 256, 256>>>(W_hh);
    wihconv_kernel<<<(4096 * 256 + 255) / 256, 256>>>(W_ih);
    gather_kernel<<<2048, 256>>>(x, emb_table);
    xproj_mma<<<dim3(256, 32), 256>>>(b_ih);
    lstm_persistent<<<NBLK, NTHR>>>(b_hh);
    final_kernel<<<BATCH, 64>>>(W1, b1, W2, b2, out);
}

// round 6
// speedup vs baseline: 4.0414x; 1.3309x over previous
#include <cuda_runtime.h>
#include <cuda_bf16.h>
#include <math.h>
#include <stdint.h>

#define HID   1024
#define EMBD  512
#define BATCH 64
#define SEQ   512
#define G4    4096
#define NBLK  128

// ===================== device scratch =====================
__device__ float    g_xproj[(size_t)SEQ * BATCH * G4];     // [t][b][4096] == [m][4096], m=t*64+b
// W_hh in m16n8k16 B-fragment order, bf16 hi/lo (recurrence):
//   u32 idx = (((jj*64 + s)*4 + g)*32 + lane)*4 + part*2 + khalf
__device__ uint32_t g_wfrag[128 * 64 * 4 * 32 * 4];        // 16 MB
// W_ih in B-fragment order, bf16 hi/lo (xproj):
//   u32 idx = ((ntile*32 + s)*32 + lane)*4 + part*2 + khalf   (ntile: 512, s: 32)
__device__ uint32_t g_wihfrag[512 * 32 * 32 * 4];          // 8 MB
// emb rows (m=t*64+b, k=0..511) in A-fragment order, bf16 hi/lo:
//   uint4 idx = ((mtile*32 + s)*32 + lane)*2 + part        (mtile: 2048, s: 32)
__device__ uint4    g_afrag[2048 * 32 * 32 * 2];           // 67 MB
// h in A-fragment order, bf16 hi/lo, double buffered:
__device__ uint32_t g_hfrag[2][64 * 4 * 32 * 8];           // 512 KB x2
__device__ float    g_hfin[BATCH * HID];
__device__ unsigned g_count;

__global__ void init_kernel() {
    if (blockIdx.x == 0 && threadIdx.x == 0) g_count = 0u;
}

// ===================== helpers =====================
__device__ __forceinline__ float sigmf(float v) { return 1.0f / (1.0f + expf(-v)); }

__device__ __forceinline__ uint32_t pack_bf16x2(float e0, float e1) {
    uint16_t u0 = __bfloat16_as_ushort(__float2bfloat16(e0));
    uint16_t u1 = __bfloat16_as_ushort(__float2bfloat16(e1));
    return (uint32_t)u0 | ((uint32_t)u1 << 16);
}

#define MMA_BF16(d, a, b0, b1) \
    asm volatile("mma.sync.aligned.m16n8k16.row.col.f32.bf16.bf16.f32 " \
        "{%0,%1,%2,%3}, {%4,%5,%6,%7}, {%8,%9}, {%0,%1,%2,%3};" \
        : "+f"((d)[0]), "+f"((d)[1]), "+f"((d)[2]), "+f"((d)[3]) \
        : "r"((a).x), "r"((a).y), "r"((a).z), "r"((a).w), "r"(b0), "r"(b1))

// ===================== W_hh -> fragment converter (unchanged) =====================
__global__ void wconv_kernel(const float* __restrict__ W_hh) {
    int id = blockIdx.x * blockDim.x + threadIdx.x;   // 4096*512
    if (id >= 4096 * 512) return;
    int n  = id >> 9;
    int k  = (id & 511) * 2;
    float2 w = *(const float2*)(W_hh + (size_t)n * HID + k);
    float hi0 = __bfloat162float(__float2bfloat16(w.x));
    float hi1 = __bfloat162float(__float2bfloat16(w.y));
    uint32_t ph = pack_bf16x2(w.x, w.y);
    uint32_t pl = pack_bf16x2(w.x - hi0, w.y - hi1);

    int g  = n >> 10, jj = (n >> 3) & 127, ul = n & 7;
    int s  = k >> 4, tig = (k >> 1) & 3, khalf = (k >> 3) & 1;
    int lane = (ul << 2) | tig;
    uint32_t base = (uint32_t)((((jj * 64 + s) * 4 + g) * 32 + lane) * 4);
    g_wfrag[base + khalf]     = ph;
    g_wfrag[base + 2 + khalf] = pl;
}

// ===================== W_ih -> fragment converter (unchanged) =====================
__global__ void wihconv_kernel(const float* __restrict__ W_ih) {
    int id = blockIdx.x * blockDim.x + threadIdx.x;   // 4096*256 k-pairs
    if (id >= 4096 * 256) return;
    int n  = id >> 8;
    int k  = (id & 255) * 2;
    float2 w = *(const float2*)(W_ih + (size_t)n * EMBD + k);
    float hi0 = __bfloat162float(__float2bfloat16(w.x));
    float hi1 = __bfloat162float(__float2bfloat16(w.y));
    uint32_t ph = pack_bf16x2(w.x, w.y);
    uint32_t pl = pack_bf16x2(w.x - hi0, w.y - hi1);

    int ntile = n >> 3, ul = n & 7;
    int s = k >> 4, tig = (k >> 1) & 3, khalf = (k >> 3) & 1;
    int lane = (ul << 2) | tig;
    uint32_t base = (uint32_t)(((ntile * 32 + s) * 32 + lane) * 4);
    g_wihfrag[base + khalf]     = ph;
    g_wihfrag[base + 2 + khalf] = pl;
}

// ===================== embedding gather -> A fragments (unchanged) =====================
__global__ void gather_kernel(const int*   __restrict__ x,
                              const float* __restrict__ emb_table) {
    __shared__ int toks[16];
    const int mtile = blockIdx.x;
    const int tid = threadIdx.x;
    const int wid = tid >> 5;
    const int lid = tid & 31;

    if (tid < 16) {
        int m = mtile * 16 + tid;
        int t = m >> 6, b = m & 63;
        toks[tid] = x[b * SEQ + t];
    }
    __syncthreads();

    const int r0 = lid >> 2;
    const int c0 = (lid & 3) * 2;
    const int tok0 = toks[r0];
    const int tok1 = toks[r0 + 8];
    const float* e0 = emb_table + (size_t)tok0 * EMBD;
    const float* e1 = emb_table + (size_t)tok1 * EMBD;

#pragma unroll
    for (int q = 0; q < 4; q++) {
        int s = wid * 4 + q;
        int kb = s * 16;
        float2 v00 = (tok0 == 0) ? make_float2(0.f, 0.f) : *(const float2*)(e0 + kb + c0);
        float2 v01 = (tok0 == 0) ? make_float2(0.f, 0.f) : *(const float2*)(e0 + kb + c0 + 8);
        float2 v10 = (tok1 == 0) ? make_float2(0.f, 0.f) : *(const float2*)(e1 + kb + c0);
        float2 v11 = (tok1 == 0) ? make_float2(0.f, 0.f) : *(const float2*)(e1 + kb + c0 + 8);

        uint4 hi, lo;
        hi.x = pack_bf16x2(v00.x, v00.y);
        hi.y = pack_bf16x2(v10.x, v10.y);
        hi.z = pack_bf16x2(v01.x, v01.y);
        hi.w = pack_bf16x2(v11.x, v11.y);
        lo.x = pack_bf16x2(v00.x - __bfloat162float(__float2bfloat16(v00.x)),
                           v00.y - __bfloat162float(__float2bfloat16(v00.y)));
        lo.y = pack_bf16x2(v10.x - __bfloat162float(__float2bfloat16(v10.x)),
                           v10.y - __bfloat162float(__float2bfloat16(v10.y)));
        lo.z = pack_bf16x2(v01.x - __bfloat162float(__float2bfloat16(v01.x)),
                           v01.y - __bfloat162float(__float2bfloat16(v01.y)));
        lo.w = pack_bf16x2(v11.x - __bfloat162float(__float2bfloat16(v11.x)),
                           v11.y - __bfloat162float(__float2bfloat16(v11.y)));

        uint4* dst = g_afrag + (((size_t)mtile * 32 + s) * 32 + lid) * 2;
        dst[0] = hi;
        dst[1] = lo;
    }
}

// ===================== xproj GEMM (HMMA, hi/lo split) — unchanged =====================
__global__ void __launch_bounds__(256, 1)
xproj_mma(const float* __restrict__ b_ih) {
    const int tid = threadIdx.x;
    const int wid = tid >> 5;
    const int lid = tid & 31;
    const int mtile = blockIdx.x * 8 + wid;
    const int nt0   = blockIdx.y * 16;

    float acc[16][4];
#pragma unroll
    for (int nf = 0; nf < 16; nf++)
#pragma unroll
        for (int c = 0; c < 4; c++) acc[nf][c] = 0.0f;

    const uint4* abase = g_afrag + ((size_t)mtile * 32) * 32 * 2 + lid * 2;
    const uint4* bbase = ((const uint4*)g_wihfrag) + ((size_t)nt0 * 32) * 32 + lid;

    for (int s = 0; s < 32; s++) {
        uint4 Ah = __ldcg(abase + (size_t)s * 64);
        uint4 Al = __ldcg(abase + (size_t)s * 64 + 1);
        const uint4* bp = bbase + (size_t)s * 32;
#pragma unroll
        for (int nf = 0; nf < 16; nf++) {
            uint4 B = __ldg(bp + (size_t)nf * 32 * 32);
            MMA_BF16(acc[nf], Ah, B.x, B.y);
            MMA_BF16(acc[nf], Ah, B.z, B.w);
            MMA_BF16(acc[nf], Al, B.x, B.y);
        }
    }

    const int row0 = mtile * 16 + (lid >> 2);
    const int cbase = (lid & 3) * 2;
    float* o0 = g_xproj + (size_t)row0 * G4;
    float* o1 = g_xproj + (size_t)(row0 + 8) * G4;
#pragma unroll
    for (int nf = 0; nf < 16; nf++) {
        int col = (nt0 + nf) * 8 + cbase;
        float2 bias = *(const float2*)(b_ih + col);
        *(float2*)(o0 + col) = make_float2(acc[nf][0] + bias.x, acc[nf][1] + bias.y);
        *(float2*)(o1 + col) = make_float2(acc[nf][2] + bias.x, acc[nf][3] + bias.y);
    }
}

// ===================== grid barrier =====================
__device__ __forceinline__ void grid_bar(unsigned target) {
    __syncthreads();
    if (threadIdx.x == 0) {
        __threadfence();
        atomicAdd(&g_count, 1u);
        while (*(volatile unsigned*)&g_count < target * NBLK) {
            __nanosleep(32);
        }
        __threadfence();
    }
    __syncthreads();
}

// ===================== persistent LSTM recurrence (HMMA, 8-warp K-split) ==========
// Block j owns gate columns {g*1024 + j*8 + ul}. 8 warps: wid = kh*4 + mt.
// Warp (kh,mt): rows 16mt..16mt+15, K-half kh (s = kh*32 .. kh*32+31).
// Warps 4-7 dump partial acc to smem; warps 0-3 reduce + LSTM update.
__global__ void __launch_bounds__(256, 1)
lstm_persistent(const float* __restrict__ b_hh) {
    __shared__ float xs[64][36];
    __shared__ float psum[4][16][32];
    __shared__ float bhs[32];

    const int j   = blockIdx.x;
    const int tid = threadIdx.x;
    const int wid = tid >> 5;
    const int lid = tid & 31;
    const int kh  = wid >> 2;              // K-half
    const int mt  = wid & 3;               // m-tile
    const int r0  = mt * 16 + (lid >> 2);
    const int tig = lid & 3;
    const int sj  = j >> 1;
    const int regbase = (j & 1) << 1;

    if (tid < 32) {
        int g = tid >> 3, ul = tid & 7;
        bhs[tid] = b_hh[g * HID + j * 8 + ul];
    }

    if (wid < 4) {
        uint32_t* hb = g_hfrag[0] + (((sj * 4 + wid) * 32 + lid) * 8);
#pragma unroll
        for (int mh = 0; mh < 2; mh++) {
            hb[regbase + mh]     = 0u;
            hb[4 + regbase + mh] = 0u;
        }
    }
    float creg[4];
#pragma unroll
    for (int q = 0; q < 4; q++) creg[q] = 0.0f;

    unsigned barnum = 0;
    grid_bar(++barnum);

    // B-fragment base for this warp's K-half (s offset folded in)
    const uint4* wbase = ((const uint4*)g_wfrag)
                       + ((size_t)j * 64 + kh * 32) * 4 * 32 + lid;

    for (int t = 0; t < SEQ; t++) {
        const int cb = t & 1, nb = cb ^ 1;

        // ---- warps 4-7 stage x_proj tile [64 b x 32 cols] into smem
        if (wid >= 4) {
            int t2 = tid - 128;
            int b = t2 >> 1;
            int g0 = (t2 & 1) * 2;
            const float* xp = g_xproj + (size_t)t * BATCH * G4 + (size_t)b * G4 + j * 8;
#pragma unroll
            for (int gg = 0; gg < 2; gg++) {
                int g = g0 + gg;
                float4 v0 = __ldcs((const float4*)(xp + g * HID));
                float4 v1 = __ldcs((const float4*)(xp + g * HID) + 1);
                *(float4*)&xs[b][g * 8]     = v0;
                *(float4*)&xs[b][g * 8 + 4] = v1;
            }
        }

        // ---- K-half loop: 32 k-steps of m16n8k16, hi/lo split (3 mma per g)
        const uint4* habase = ((const uint4*)g_hfrag[cb])
                            + ((size_t)kh * 32 * 4 + mt) * 64 + lid * 2;
        uint4 Ab[2][4][2];
        uint4 Bb[2][4];
        float acc[4][4];
#pragma unroll
        for (int g = 0; g < 4; g++)
#pragma unroll
            for (int c = 0; c < 4; c++) acc[g][c] = 0.0f;

#pragma unroll
        for (int u = 0; u < 4; u++) {
            const uint4* p = habase + (size_t)u * 256;   // s stride = 4*32*2 uint4
            Ab[0][u][0] = __ldcg(p);
            Ab[0][u][1] = __ldcg(p + 1);
        }
#pragma unroll
        for (int g = 0; g < 4; g++) Bb[0][g] = __ldg(wbase + g * 32);

#pragma unroll 8
        for (int s = 0; s < 32; s++) {
            const int u  = s & 3;
            const int ab = (s >> 2) & 1;
            const int bb = s & 1;
            if (s < 31) {
                const uint4* wp = wbase + (size_t)(s + 1) * 128;
#pragma unroll
                for (int g = 0; g < 4; g++) Bb[bb ^ 1][g] = __ldg(wp + g * 32);
            }
            if (s < 28) {
                const uint4* p = habase + (size_t)(s + 4) * 256;
                Ab[ab ^ 1][u][0] = __ldcg(p);
                Ab[ab ^ 1][u][1] = __ldcg(p + 1);
            }
            uint4 A0 = Ab[ab][u][0];
            uint4 A1 = Ab[ab][u][1];
#pragma unroll
            for (int g = 0; g < 4; g++) {
                uint4 B = Bb[bb][g];
                MMA_BF16(acc[g], A0, B.x, B.y);
                MMA_BF16(acc[g], A0, B.z, B.w);
                MMA_BF16(acc[g], A1, B.x, B.y);
            }
        }

        // ---- warps 4-7: partials -> smem
        if (wid >= 4) {
#pragma unroll
            for (int g = 0; g < 4; g++)
#pragma unroll
                for (int c = 0; c < 4; c++)
                    psum[mt][g * 4 + c][lid] = acc[g][c];
        }
        __syncthreads();

        // ---- warps 0-3: reduce + LSTM update
        if (wid < 4) {
#pragma unroll
            for (int g = 0; g < 4; g++)
#pragma unroll
                for (int c = 0; c < 4; c++)
                    acc[g][c] += psum[mt][g * 4 + c][lid];

            uint32_t* hb = g_hfrag[nb] + (((sj * 4 + mt) * 32 + lid) * 8);
#pragma unroll
            for (int mh = 0; mh < 2; mh++) {
                int row = r0 + 8 * mh;
                float h2[2];
#pragma unroll
                for (int cbit = 0; cbit < 2; cbit++) {
                    int ci = mh * 2 + cbit;
                    int ul = 2 * tig + cbit;
                    float ig = acc[0][ci] + xs[row][ul]      + bhs[ul];
                    float fg = acc[1][ci] + xs[row][8 + ul]  + bhs[8 + ul];
                    float gg = acc[2][ci] + xs[row][16 + ul] + bhs[16 + ul];
                    float og = acc[3][ci] + xs[row][24 + ul] + bhs[24 + ul];
                    float cn = sigmf(fg) * creg[ci] + sigmf(ig) * tanhf(gg);
                    creg[ci] = cn;
                    h2[cbit] = sigmf(og) * tanhf(cn);
                }
                float hi0 = __bfloat162float(__float2bfloat16(h2[0]));
                float hi1 = __bfloat162float(__float2bfloat16(h2[1]));
                hb[regbase + mh]     = pack_bf16x2(h2[0], h2[1]);
                hb[4 + regbase + mh] = pack_bf16x2(h2[0] - hi0, h2[1] - hi1);
                if (t == SEQ - 1) {
                    *(float2*)(g_hfin + row * HID + j * 8 + 2 * tig) =
                        make_float2(h2[0], h2[1]);
                }
            }
        }
        grid_bar(++barnum);
    }
}

// ===================== head (unchanged) =====================
__global__ void final_kernel(const float* __restrict__ W1,
                             const float* __restrict__ b1,
                             const float* __restrict__ W2,
                             const float* __restrict__ b2,
                             float* __restrict__ out) {
    __shared__ float red[64];
    int b = blockIdx.x;
    int jj = threadIdx.x;
    const float* hrow = g_hfin + b * HID;
    const float* wrow = W1 + jj * HID;
    float s = 0.0f;
    for (int k = 0; k < HID; k++) s = fmaf(hrow[k], wrow[k], s);
    float hid = fmaxf(s + b1[jj], 0.0f);
    red[jj] = hid * W2[jj];
    __syncthreads();
    if (jj == 0) {
        float o = b2[0];
#pragma unroll
        for (int q = 0; q < 64; q++) o += red[q];
        out[b] = o;
    }
}

// ===================== launch =====================
extern "C" void kernel_launch(void* const* d_in, const int* in_sizes, int n_in,
                              void* d_out, int out_size) {
    (void)in_sizes; (void)n_in; (void)out_size;
    const int*   x         = (const int*)  d_in[0];
    const float* emb_table = (const float*)d_in[2];
    const float* W_ih      = (const float*)d_in[3];
    const float* b_ih      = (const float*)d_in[4];
    const float* W_hh      = (const float*)d_in[5];
    const float* b_hh      = (const float*)d_in[6];
    const float* W1        = (const float*)d_in[7];
    const float* b1        = (const float*)d_in[8];
    const float* W2        = (const float*)d_in[9];
    const float* b2        = (const float*)d_in[10];
    float* out = (float*)d_out;

    init_kernel<<<1, 32>>>();
    wconv_kernel<<<(4096 * 512 + 255) / 256, 256>>>(W_hh);
    wihconv_kernel<<<(4096 * 256 + 255) / 256, 256>>>(W_ih);
    gather_kernel<<<2048, 256>>>(x, emb_table);
    xproj_mma<<<dim3(256, 32), 256>>>(b_ih);
    lstm_persistent<<<NBLK, 256>>>(b_hh);
    final_kernel<<<BATCH, 64>>>(W1, b1, W2, b2, out);
}

// round 7
// speedup vs baseline: 4.0803x; 1.0096x over previous
#include <cuda_runtime.h>
#include <cuda_bf16.h>
#include <math.h>
#include <stdint.h>

#define HID   1024
#define EMBD  512
#define BATCH 64
#define SEQ   512
#define G4    4096
#define NBLK  128

// ===================== device scratch =====================
__device__ float    g_xproj[(size_t)SEQ * BATCH * G4];     // [t][b][4096] == [m][4096], m=t*64+b
// W_hh in m16n8k16 B-fragment order, bf16 hi/lo (recurrence):
//   u32 idx = (((jj*64 + s)*4 + g)*32 + lane)*4 + part*2 + khalf
__device__ uint32_t g_wfrag[128 * 64 * 4 * 32 * 4];        // 16 MB
// W_ih in B-fragment order, bf16 hi/lo (xproj):
//   u32 idx = ((ntile*32 + s)*32 + lane)*4 + part*2 + khalf   (ntile: 512, s: 32)
__device__ uint32_t g_wihfrag[512 * 32 * 32 * 4];          // 8 MB
// emb rows (m=t*64+b, k=0..511) in A-fragment order, bf16 hi/lo:
//   uint4 idx = ((mtile*32 + s)*32 + lane)*2 + part        (mtile: 2048, s: 32)
__device__ uint4    g_afrag[2048 * 32 * 32 * 2];           // 67 MB
// h in A-fragment order, bf16 hi/lo, double buffered:
__device__ uint32_t g_hfrag[2][64 * 4 * 32 * 8];           // 512 KB x2
__device__ float    g_hfin[BATCH * HID];
__device__ unsigned g_count;

__global__ void init_kernel() {
    if (blockIdx.x == 0 && threadIdx.x == 0) g_count = 0u;
}

// ===================== helpers =====================
__device__ __forceinline__ float sigmf(float v) { return 1.0f / (1.0f + expf(-v)); }

__device__ __forceinline__ uint32_t pack_bf16x2(float e0, float e1) {
    uint16_t u0 = __bfloat16_as_ushort(__float2bfloat16(e0));
    uint16_t u1 = __bfloat16_as_ushort(__float2bfloat16(e1));
    return (uint32_t)u0 | ((uint32_t)u1 << 16);
}

#define MMA_BF16(d, a, b0, b1) \
    asm volatile("mma.sync.aligned.m16n8k16.row.col.f32.bf16.bf16.f32 " \
        "{%0,%1,%2,%3}, {%4,%5,%6,%7}, {%8,%9}, {%0,%1,%2,%3};" \
        : "+f"((d)[0]), "+f"((d)[1]), "+f"((d)[2]), "+f"((d)[3]) \
        : "r"((a).x), "r"((a).y), "r"((a).z), "r"((a).w), "r"(b0), "r"(b1))

// ===================== W_hh -> fragment converter (unchanged) =====================
__global__ void wconv_kernel(const float* __restrict__ W_hh) {
    int id = blockIdx.x * blockDim.x + threadIdx.x;   // 4096*512
    if (id >= 4096 * 512) return;
    int n  = id >> 9;
    int k  = (id & 511) * 2;
    float2 w = *(const float2*)(W_hh + (size_t)n * HID + k);
    float hi0 = __bfloat162float(__float2bfloat16(w.x));
    float hi1 = __bfloat162float(__float2bfloat16(w.y));
    uint32_t ph = pack_bf16x2(w.x, w.y);
    uint32_t pl = pack_bf16x2(w.x - hi0, w.y - hi1);

    int g  = n >> 10, jj = (n >> 3) & 127, ul = n & 7;
    int s  = k >> 4, tig = (k >> 1) & 3, khalf = (k >> 3) & 1;
    int lane = (ul << 2) | tig;
    uint32_t base = (uint32_t)((((jj * 64 + s) * 4 + g) * 32 + lane) * 4);
    g_wfrag[base + khalf]     = ph;
    g_wfrag[base + 2 + khalf] = pl;
}

// ===================== W_ih -> fragment converter (unchanged) =====================
__global__ void wihconv_kernel(const float* __restrict__ W_ih) {
    int id = blockIdx.x * blockDim.x + threadIdx.x;   // 4096*256 k-pairs
    if (id >= 4096 * 256) return;
    int n  = id >> 8;
    int k  = (id & 255) * 2;
    float2 w = *(const float2*)(W_ih + (size_t)n * EMBD + k);
    float hi0 = __bfloat162float(__float2bfloat16(w.x));
    float hi1 = __bfloat162float(__float2bfloat16(w.y));
    uint32_t ph = pack_bf16x2(w.x, w.y);
    uint32_t pl = pack_bf16x2(w.x - hi0, w.y - hi1);

    int ntile = n >> 3, ul = n & 7;
    int s = k >> 4, tig = (k >> 1) & 3, khalf = (k >> 3) & 1;
    int lane = (ul << 2) | tig;
    uint32_t base = (uint32_t)(((ntile * 32 + s) * 32 + lane) * 4);
    g_wihfrag[base + khalf]     = ph;
    g_wihfrag[base + 2 + khalf] = pl;
}

// ===================== embedding gather -> A fragments (unchanged) =====================
__global__ void gather_kernel(const int*   __restrict__ x,
                              const float* __restrict__ emb_table) {
    __shared__ int toks[16];
    const int mtile = blockIdx.x;
    const int tid = threadIdx.x;
    const int wid = tid >> 5;
    const int lid = tid & 31;

    if (tid < 16) {
        int m = mtile * 16 + tid;
        int t = m >> 6, b = m & 63;
        toks[tid] = x[b * SEQ + t];
    }
    __syncthreads();

    const int r0 = lid >> 2;
    const int c0 = (lid & 3) * 2;
    const int tok0 = toks[r0];
    const int tok1 = toks[r0 + 8];
    const float* e0 = emb_table + (size_t)tok0 * EMBD;
    const float* e1 = emb_table + (size_t)tok1 * EMBD;

#pragma unroll
    for (int q = 0; q < 4; q++) {
        int s = wid * 4 + q;
        int kb = s * 16;
        float2 v00 = (tok0 == 0) ? make_float2(0.f, 0.f) : *(const float2*)(e0 + kb + c0);
        float2 v01 = (tok0 == 0) ? make_float2(0.f, 0.f) : *(const float2*)(e0 + kb + c0 + 8);
        float2 v10 = (tok1 == 0) ? make_float2(0.f, 0.f) : *(const float2*)(e1 + kb + c0);
        float2 v11 = (tok1 == 0) ? make_float2(0.f, 0.f) : *(const float2*)(e1 + kb + c0 + 8);

        uint4 hi, lo;
        hi.x = pack_bf16x2(v00.x, v00.y);
        hi.y = pack_bf16x2(v10.x, v10.y);
        hi.z = pack_bf16x2(v01.x, v01.y);
        hi.w = pack_bf16x2(v11.x, v11.y);
        lo.x = pack_bf16x2(v00.x - __bfloat162float(__float2bfloat16(v00.x)),
                           v00.y - __bfloat162float(__float2bfloat16(v00.y)));
        lo.y = pack_bf16x2(v10.x - __bfloat162float(__float2bfloat16(v10.x)),
                           v10.y - __bfloat162float(__float2bfloat16(v10.y)));
        lo.z = pack_bf16x2(v01.x - __bfloat162float(__float2bfloat16(v01.x)),
                           v01.y - __bfloat162float(__float2bfloat16(v01.y)));
        lo.w = pack_bf16x2(v11.x - __bfloat162float(__float2bfloat16(v11.x)),
                           v11.y - __bfloat162float(__float2bfloat16(v11.y)));

        uint4* dst = g_afrag + (((size_t)mtile * 32 + s) * 32 + lid) * 2;
        dst[0] = hi;
        dst[1] = lo;
    }
}

// ===================== xproj GEMM (HMMA, hi/lo split, nf=32) =====================
// M=32768, N=4096, K=512. grid (256, 16), 8 warps.
// warp: mtile = bx*8+wid (16 rows), 32 n8-frags (256 cols), 32 ksteps.
__global__ void __launch_bounds__(256, 1)
xproj_mma(const float* __restrict__ b_ih) {
    const int tid = threadIdx.x;
    const int wid = tid >> 5;
    const int lid = tid & 31;
    const int mtile = blockIdx.x * 8 + wid;
    const int nt0   = blockIdx.y * 32;

    float acc[32][4];
#pragma unroll
    for (int nf = 0; nf < 32; nf++)
#pragma unroll
        for (int c = 0; c < 4; c++) acc[nf][c] = 0.0f;

    const uint4* abase = g_afrag + ((size_t)mtile * 32) * 32 * 2 + lid * 2;
    const uint4* bbase = ((const uint4*)g_wihfrag) + ((size_t)nt0 * 32) * 32 + lid;

    for (int s = 0; s < 32; s++) {
        uint4 Ah = __ldcg(abase + (size_t)s * 64);
        uint4 Al = __ldcg(abase + (size_t)s * 64 + 1);
        const uint4* bp = bbase + (size_t)s * 32;
#pragma unroll
        for (int nf = 0; nf < 32; nf++) {
            uint4 B = __ldg(bp + (size_t)nf * 32 * 32);
            MMA_BF16(acc[nf], Ah, B.x, B.y);
            MMA_BF16(acc[nf], Ah, B.z, B.w);
            MMA_BF16(acc[nf], Al, B.x, B.y);
        }
    }

    const int row0 = mtile * 16 + (lid >> 2);
    const int cbase = (lid & 3) * 2;
    float* o0 = g_xproj + (size_t)row0 * G4;
    float* o1 = g_xproj + (size_t)(row0 + 8) * G4;
#pragma unroll
    for (int nf = 0; nf < 32; nf++) {
        int col = (nt0 + nf) * 8 + cbase;
        float2 bias = *(const float2*)(b_ih + col);
        *(float2*)(o0 + col) = make_float2(acc[nf][0] + bias.x, acc[nf][1] + bias.y);
        *(float2*)(o1 + col) = make_float2(acc[nf][2] + bias.x, acc[nf][3] + bias.y);
    }
}

// ===================== grid barrier (release/acquire, no membar.gpu) ===========
__device__ __forceinline__ void grid_bar(unsigned target) {
    __syncthreads();
    if (threadIdx.x == 0) {
        asm volatile("red.release.gpu.global.add.u32 [%0], %1;"
                     :: "l"(&g_count), "r"(1u) : "memory");
        unsigned v;
        while (true) {
            asm volatile("ld.acquire.gpu.global.u32 %0, [%1];"
                         : "=r"(v) : "l"(&g_count) : "memory");
            if (v >= target * NBLK) break;
            __nanosleep(32);
        }
    }
    __syncthreads();
}

// ===================== persistent LSTM recurrence (HMMA, 8-warp K-split) ==========
__global__ void __launch_bounds__(256, 1)
lstm_persistent(const float* __restrict__ b_hh) {
    __shared__ float xs[64][36];
    __shared__ float psum[4][16][32];
    __shared__ float bhs[32];

    const int j   = blockIdx.x;
    const int tid = threadIdx.x;
    const int wid = tid >> 5;
    const int lid = tid & 31;
    const int kh  = wid >> 2;              // K-half
    const int mt  = wid & 3;               // m-tile
    const int r0  = mt * 16 + (lid >> 2);
    const int tig = lid & 3;
    const int sj  = j >> 1;
    const int regbase = (j & 1) << 1;

    if (tid < 32) {
        int g = tid >> 3, ul = tid & 7;
        bhs[tid] = b_hh[g * HID + j * 8 + ul];
    }

    if (wid < 4) {
        uint32_t* hb = g_hfrag[0] + (((sj * 4 + wid) * 32 + lid) * 8);
#pragma unroll
        for (int mh = 0; mh < 2; mh++) {
            hb[regbase + mh]     = 0u;
            hb[4 + regbase + mh] = 0u;
        }
    }
    float creg[4];
#pragma unroll
    for (int q = 0; q < 4; q++) creg[q] = 0.0f;

    unsigned barnum = 0;
    grid_bar(++barnum);

    const uint4* wbase = ((const uint4*)g_wfrag)
                       + ((size_t)j * 64 + kh * 32) * 4 * 32 + lid;

    for (int t = 0; t < SEQ; t++) {
        const int cb = t & 1, nb = cb ^ 1;

        // ---- warps 4-7 stage x_proj tile [64 b x 32 cols] into smem
        if (wid >= 4) {
            int t2 = tid - 128;
            int b = t2 >> 1;
            int g0 = (t2 & 1) * 2;
            const float* xp = g_xproj + (size_t)t * BATCH * G4 + (size_t)b * G4 + j * 8;
#pragma unroll
            for (int gg = 0; gg < 2; gg++) {
                int g = g0 + gg;
                float4 v0 = __ldcs((const float4*)(xp + g * HID));
                float4 v1 = __ldcs((const float4*)(xp + g * HID) + 1);
                *(float4*)&xs[b][g * 8]     = v0;
                *(float4*)&xs[b][g * 8 + 4] = v1;
            }
        }

        // ---- K-half loop: 32 k-steps of m16n8k16, hi/lo split (3 mma per g)
        const uint4* habase = ((const uint4*)g_hfrag[cb])
                            + ((size_t)kh * 32 * 4 + mt) * 64 + lid * 2;
        uint4 Ab[2][4][2];
        uint4 Bb[2][4];
        float acc[4][4];
#pragma unroll
        for (int g = 0; g < 4; g++)
#pragma unroll
            for (int c = 0; c < 4; c++) acc[g][c] = 0.0f;

#pragma unroll
        for (int u = 0; u < 4; u++) {
            const uint4* p = habase + (size_t)u * 256;
            Ab[0][u][0] = __ldcg(p);
            Ab[0][u][1] = __ldcg(p + 1);
        }
#pragma unroll
        for (int g = 0; g < 4; g++) Bb[0][g] = __ldg(wbase + g * 32);

#pragma unroll 8
        for (int s = 0; s < 32; s++) {
            const int u  = s & 3;
            const int ab = (s >> 2) & 1;
            const int bb = s & 1;
            if (s < 31) {
                const uint4* wp = wbase + (size_t)(s + 1) * 128;
#pragma unroll
                for (int g = 0; g < 4; g++) Bb[bb ^ 1][g] = __ldg(wp + g * 32);
            }
            if (s < 28) {
                const uint4* p = habase + (size_t)(s + 4) * 256;
                Ab[ab ^ 1][u][0] = __ldcg(p);
                Ab[ab ^ 1][u][1] = __ldcg(p + 1);
            }
            uint4 A0 = Ab[ab][u][0];
            uint4 A1 = Ab[ab][u][1];
#pragma unroll
            for (int g = 0; g < 4; g++) {
                uint4 B = Bb[bb][g];
                MMA_BF16(acc[g], A0, B.x, B.y);
                MMA_BF16(acc[g], A0, B.z, B.w);
                MMA_BF16(acc[g], A1, B.x, B.y);
            }
        }

        // ---- warps 4-7: partials -> smem
        if (wid >= 4) {
#pragma unroll
            for (int g = 0; g < 4; g++)
#pragma unroll
                for (int c = 0; c < 4; c++)
                    psum[mt][g * 4 + c][lid] = acc[g][c];
        }
        __syncthreads();

        // ---- warps 0-3: reduce + LSTM update
        if (wid < 4) {
#pragma unroll
            for (int g = 0; g < 4; g++)
#pragma unroll
                for (int c = 0; c < 4; c++)
                    acc[g][c] += psum[mt][g * 4 + c][lid];

            uint32_t* hb = g_hfrag[nb] + (((sj * 4 + mt) * 32 + lid) * 8);
#pragma unroll
            for (int mh = 0; mh < 2; mh++) {
                int row = r0 + 8 * mh;
                float h2[2];
#pragma unroll
                for (int cbit = 0; cbit < 2; cbit++) {
                    int ci = mh * 2 + cbit;
                    int ul = 2 * tig + cbit;
                    float ig = acc[0][ci] + xs[row][ul]      + bhs[ul];
                    float fg = acc[1][ci] + xs[row][8 + ul]  + bhs[8 + ul];
                    float gg = acc[2][ci] + xs[row][16 + ul] + bhs[16 + ul];
                    float og = acc[3][ci] + xs[row][24 + ul] + bhs[24 + ul];
                    float cn = sigmf(fg) * creg[ci] + sigmf(ig) * tanhf(gg);
                    creg[ci] = cn;
                    h2[cbit] = sigmf(og) * tanhf(cn);
                }
                float hi0 = __bfloat162float(__float2bfloat16(h2[0]));
                float hi1 = __bfloat162float(__float2bfloat16(h2[1]));
                hb[regbase + mh]     = pack_bf16x2(h2[0], h2[1]);
                hb[4 + regbase + mh] = pack_bf16x2(h2[0] - hi0, h2[1] - hi1);
                if (t == SEQ - 1) {
                    *(float2*)(g_hfin + row * HID + j * 8 + 2 * tig) =
                        make_float2(h2[0], h2[1]);
                }
            }
        }
        grid_bar(++barnum);
    }
}

// ===================== head (parallel warp-reduce) =====================
__global__ void final_kernel(const float* __restrict__ W1,
                             const float* __restrict__ b1,
                             const float* __restrict__ W2,
                             const float* __restrict__ b2,
                             float* __restrict__ out) {
    __shared__ float hidden[64];
    const int b   = blockIdx.x;
    const int tid = threadIdx.x;
    const int wid = tid >> 5;
    const int lid = tid & 31;
    const float* hrow = g_hfin + b * HID;

#pragma unroll
    for (int q = 0; q < 8; q++) {
        int jj = wid + q * 8;
        const float* wrow = W1 + jj * HID;
        float s = 0.0f;
#pragma unroll 8
        for (int k = lid; k < HID; k += 32) s = fmaf(hrow[k], wrow[k], s);
#pragma unroll
        for (int o = 16; o; o >>= 1) s += __shfl_xor_sync(0xFFFFFFFFu, s, o);
        if (lid == 0) hidden[jj] = fmaxf(s + b1[jj], 0.0f) * W2[jj];
    }
    __syncthreads();
    if (wid == 0) {
        float v = hidden[lid] + hidden[lid + 32];
#pragma unroll
        for (int o = 16; o; o >>= 1) v += __shfl_xor_sync(0xFFFFFFFFu, v, o);
        if (lid == 0) out[b] = v + b2[0];
    }
}

// ===================== launch =====================
extern "C" void kernel_launch(void* const* d_in, const int* in_sizes, int n_in,
                              void* d_out, int out_size) {
    (void)in_sizes; (void)n_in; (void)out_size;
    const int*   x         = (const int*)  d_in[0];
    const float* emb_table = (const float*)d_in[2];
    const float* W_ih      = (const float*)d_in[3];
    const float* b_ih      = (const float*)d_in[4];
    const float* W_hh      = (const float*)d_in[5];
    const float* b_hh      = (const float*)d_in[6];
    const float* W1        = (const float*)d_in[7];
    const float* b1        = (const float*)d_in[8];
    const float* W2        = (const float*)d_in[9];
    const float* b2        = (const float*)d_in[10];
    float* out = (float*)d_out;

    init_kernel<<<1, 32>>>();
    wconv_kernel<<<(4096 * 512 + 255) / 256, 256>>>(W_hh);
    wihconv_kernel<<<(4096 * 256 + 255) / 256, 256>>>(W_ih);
    gather_kernel<<<2048, 256>>>(x, emb_table);
    xproj_mma<<<dim3(256, 16), 256>>>(b_ih);
    lstm_persistent<<<NBLK, 256>>>(b_hh);
    final_kernel<<<BATCH, 256>>>(W1, b1, W2, b2, out);
}

// round 8
// speedup vs baseline: 4.6799x; 1.1470x over previous
#include <cuda_runtime.h>
#include <cuda_bf16.h>
#include <math.h>
#include <stdint.h>

#define HID   1024
#define EMBD  512
#define BATCH 64
#define SEQ   512
#define G4    4096
#define NBLK  128

// ===================== device scratch =====================
__device__ float    g_xproj[(size_t)SEQ * BATCH * G4];     // [t][b][4096] == [m][4096], m=t*64+b
// W_hh in m16n8k16 B-fragment order, bf16 hi/lo (recurrence):
//   u32 idx = (((jj*64 + s)*4 + g)*32 + lane)*4 + part*2 + khalf
__device__ uint32_t g_wfrag[128 * 64 * 4 * 32 * 4];        // 16 MB
// W_ih in B-fragment order, bf16 hi/lo (xproj):
//   u32 idx = ((ntile*32 + s)*32 + lane)*4 + part*2 + khalf   (ntile: 512, s: 32)
__device__ uint32_t g_wihfrag[512 * 32 * 32 * 4];          // 8 MB
// emb rows (m=t*64+b, k=0..511) in A-fragment order, bf16 hi/lo:
//   uint4 idx = ((mtile*32 + s)*32 + lane)*2 + part        (mtile: 2048, s: 32)
__device__ uint4    g_afrag[2048 * 32 * 32 * 2];           // 67 MB
// h in A-fragment order, bf16 hi/lo, double buffered:
__device__ uint32_t g_hfrag[2][64 * 4 * 32 * 8];           // 512 KB x2
__device__ float    g_hfin[BATCH * HID];
__device__ unsigned g_count;

__global__ void init_kernel() {
    if (blockIdx.x == 0 && threadIdx.x == 0) g_count = 0u;
}

// ===================== helpers =====================
__device__ __forceinline__ float sigmf(float v) { return 1.0f / (1.0f + expf(-v)); }

__device__ __forceinline__ uint32_t pack_bf16x2(float e0, float e1) {
    uint16_t u0 = __bfloat16_as_ushort(__float2bfloat16(e0));
    uint16_t u1 = __bfloat16_as_ushort(__float2bfloat16(e1));
    return (uint32_t)u0 | ((uint32_t)u1 << 16);
}

#define MMA_BF16(d, a, b0, b1) \
    asm volatile("mma.sync.aligned.m16n8k16.row.col.f32.bf16.bf16.f32 " \
        "{%0,%1,%2,%3}, {%4,%5,%6,%7}, {%8,%9}, {%0,%1,%2,%3};" \
        : "+f"((d)[0]), "+f"((d)[1]), "+f"((d)[2]), "+f"((d)[3]) \
        : "r"((a).x), "r"((a).y), "r"((a).z), "r"((a).w), "r"(b0), "r"(b1))

// ===================== W_hh -> fragment converter (unchanged) =====================
__global__ void wconv_kernel(const float* __restrict__ W_hh) {
    int id = blockIdx.x * blockDim.x + threadIdx.x;   // 4096*512
    if (id >= 4096 * 512) return;
    int n  = id >> 9;
    int k  = (id & 511) * 2;
    float2 w = *(const float2*)(W_hh + (size_t)n * HID + k);
    float hi0 = __bfloat162float(__float2bfloat16(w.x));
    float hi1 = __bfloat162float(__float2bfloat16(w.y));
    uint32_t ph = pack_bf16x2(w.x, w.y);
    uint32_t pl = pack_bf16x2(w.x - hi0, w.y - hi1);

    int g  = n >> 10, jj = (n >> 3) & 127, ul = n & 7;
    int s  = k >> 4, tig = (k >> 1) & 3, khalf = (k >> 3) & 1;
    int lane = (ul << 2) | tig;
    uint32_t base = (uint32_t)((((jj * 64 + s) * 4 + g) * 32 + lane) * 4);
    g_wfrag[base + khalf]     = ph;
    g_wfrag[base + 2 + khalf] = pl;
}

// ===================== W_ih -> fragment converter (unchanged) =====================
__global__ void wihconv_kernel(const float* __restrict__ W_ih) {
    int id = blockIdx.x * blockDim.x + threadIdx.x;   // 4096*256 k-pairs
    if (id >= 4096 * 256) return;
    int n  = id >> 8;
    int k  = (id & 255) * 2;
    float2 w = *(const float2*)(W_ih + (size_t)n * EMBD + k);
    float hi0 = __bfloat162float(__float2bfloat16(w.x));
    float hi1 = __bfloat162float(__float2bfloat16(w.y));
    uint32_t ph = pack_bf16x2(w.x, w.y);
    uint32_t pl = pack_bf16x2(w.x - hi0, w.y - hi1);

    int ntile = n >> 3, ul = n & 7;
    int s = k >> 4, tig = (k >> 1) & 3, khalf = (k >> 3) & 1;
    int lane = (ul << 2) | tig;
    uint32_t base = (uint32_t)(((ntile * 32 + s) * 32 + lane) * 4);
    g_wihfrag[base + khalf]     = ph;
    g_wihfrag[base + 2 + khalf] = pl;
}

// ===================== embedding gather -> A fragments (unchanged) =====================
__global__ void gather_kernel(const int*   __restrict__ x,
                              const float* __restrict__ emb_table) {
    __shared__ int toks[16];
    const int mtile = blockIdx.x;
    const int tid = threadIdx.x;
    const int wid = tid >> 5;
    const int lid = tid & 31;

    if (tid < 16) {
        int m = mtile * 16 + tid;
        int t = m >> 6, b = m & 63;
        toks[tid] = x[b * SEQ + t];
    }
    __syncthreads();

    const int r0 = lid >> 2;
    const int c0 = (lid & 3) * 2;
    const int tok0 = toks[r0];
    const int tok1 = toks[r0 + 8];
    const float* e0 = emb_table + (size_t)tok0 * EMBD;
    const float* e1 = emb_table + (size_t)tok1 * EMBD;

#pragma unroll
    for (int q = 0; q < 4; q++) {
        int s = wid * 4 + q;
        int kb = s * 16;
        float2 v00 = (tok0 == 0) ? make_float2(0.f, 0.f) : *(const float2*)(e0 + kb + c0);
        float2 v01 = (tok0 == 0) ? make_float2(0.f, 0.f) : *(const float2*)(e0 + kb + c0 + 8);
        float2 v10 = (tok1 == 0) ? make_float2(0.f, 0.f) : *(const float2*)(e1 + kb + c0);
        float2 v11 = (tok1 == 0) ? make_float2(0.f, 0.f) : *(const float2*)(e1 + kb + c0 + 8);

        uint4 hi, lo;
        hi.x = pack_bf16x2(v00.x, v00.y);
        hi.y = pack_bf16x2(v10.x, v10.y);
        hi.z = pack_bf16x2(v01.x, v01.y);
        hi.w = pack_bf16x2(v11.x, v11.y);
        lo.x = pack_bf16x2(v00.x - __bfloat162float(__float2bfloat16(v00.x)),
                           v00.y - __bfloat162float(__float2bfloat16(v00.y)));
        lo.y = pack_bf16x2(v10.x - __bfloat162float(__float2bfloat16(v10.x)),
                           v10.y - __bfloat162float(__float2bfloat16(v10.y)));
        lo.z = pack_bf16x2(v01.x - __bfloat162float(__float2bfloat16(v01.x)),
                           v01.y - __bfloat162float(__float2bfloat16(v01.y)));
        lo.w = pack_bf16x2(v11.x - __bfloat162float(__float2bfloat16(v11.x)),
                           v11.y - __bfloat162float(__float2bfloat16(v11.y)));

        uint4* dst = g_afrag + (((size_t)mtile * 32 + s) * 32 + lid) * 2;
        dst[0] = hi;
        dst[1] = lo;
    }
}

// ===================== xproj GEMM (HMMA, hi/lo split, nf=32) — unchanged ==========
__global__ void __launch_bounds__(256, 1)
xproj_mma(const float* __restrict__ b_ih) {
    const int tid = threadIdx.x;
    const int wid = tid >> 5;
    const int lid = tid & 31;
    const int mtile = blockIdx.x * 8 + wid;
    const int nt0   = blockIdx.y * 32;

    float acc[32][4];
#pragma unroll
    for (int nf = 0; nf < 32; nf++)
#pragma unroll
        for (int c = 0; c < 4; c++) acc[nf][c] = 0.0f;

    const uint4* abase = g_afrag + ((size_t)mtile * 32) * 32 * 2 + lid * 2;
    const uint4* bbase = ((const uint4*)g_wihfrag) + ((size_t)nt0 * 32) * 32 + lid;

    for (int s = 0; s < 32; s++) {
        uint4 Ah = __ldcg(abase + (size_t)s * 64);
        uint4 Al = __ldcg(abase + (size_t)s * 64 + 1);
        const uint4* bp = bbase + (size_t)s * 32;
#pragma unroll
        for (int nf = 0; nf < 32; nf++) {
            uint4 B = __ldg(bp + (size_t)nf * 32 * 32);
            MMA_BF16(acc[nf], Ah, B.x, B.y);
            MMA_BF16(acc[nf], Ah, B.z, B.w);
            MMA_BF16(acc[nf], Al, B.x, B.y);
        }
    }

    const int row0 = mtile * 16 + (lid >> 2);
    const int cbase = (lid & 3) * 2;
    float* o0 = g_xproj + (size_t)row0 * G4;
    float* o1 = g_xproj + (size_t)(row0 + 8) * G4;
#pragma unroll
    for (int nf = 0; nf < 32; nf++) {
        int col = (nt0 + nf) * 8 + cbase;
        float2 bias = *(const float2*)(b_ih + col);
        *(float2*)(o0 + col) = make_float2(acc[nf][0] + bias.x, acc[nf][1] + bias.y);
        *(float2*)(o1 + col) = make_float2(acc[nf][2] + bias.x, acc[nf][3] + bias.y);
    }
}

// ===================== grid barrier (release/acquire) =====================
__device__ __forceinline__ void grid_bar(unsigned target) {
    __syncthreads();
    if (threadIdx.x == 0) {
        asm volatile("red.release.gpu.global.add.u32 [%0], %1;"
                     :: "l"(&g_count), "r"(1u) : "memory");
        unsigned v;
        while (true) {
            asm volatile("ld.acquire.gpu.global.u32 %0, [%1];"
                         : "=r"(v) : "l"(&g_count) : "memory");
            if (v >= target * NBLK) break;
            __nanosleep(32);
        }
    }
    __syncthreads();
}

// ===================== persistent LSTM recurrence (HMMA, 16-warp 4-way K-split) ===
// Block j owns gate columns {g*1024 + j*8 + ul}. 16 warps: wid = kh*4 + mt.
// Warp (kh,mt): rows 16mt..16mt+15, K-quarter kh (s = kh*16 .. kh*16+15).
// Warps kh>=1 dump partial acc to psum; warps kh==0 reduce + LSTM update.
__global__ void __launch_bounds__(512, 1)
lstm_persistent(const float* __restrict__ b_hh) {
    __shared__ float xs[64][36];
    __shared__ float psum[3][4][16][32];
    __shared__ float bhs[32];

    const int j   = blockIdx.x;
    const int tid = threadIdx.x;
    const int wid = tid >> 5;
    const int lid = tid & 31;
    const int kh  = wid >> 2;              // K-quarter 0..3
    const int mt  = wid & 3;               // m-tile
    const int r0  = mt * 16 + (lid >> 2);
    const int tig = lid & 3;
    const int sj  = j >> 1;
    const int regbase = (j & 1) << 1;

    if (tid < 32) {
        int g = tid >> 3, ul = tid & 7;
        bhs[tid] = b_hh[g * HID + j * 8 + ul];
    }

    if (wid < 4) {
        uint32_t* hb = g_hfrag[0] + (((sj * 4 + wid) * 32 + lid) * 8);
#pragma unroll
        for (int mh = 0; mh < 2; mh++) {
            hb[regbase + mh]     = 0u;
            hb[4 + regbase + mh] = 0u;
        }
    }
    float creg[4];
#pragma unroll
    for (int q = 0; q < 4; q++) creg[q] = 0.0f;

    unsigned barnum = 0;
    grid_bar(++barnum);

    // B-fragment base for this warp's K-quarter (uint4 view; per-s stride 128, per-g 32)
    const uint4* wbase = ((const uint4*)g_wfrag)
                       + ((size_t)j * 64 + kh * 16) * 128 + lid;

    for (int t = 0; t < SEQ; t++) {
        const int cb = t & 1, nb = cb ^ 1;

        // ---- warps 8-15 stage x_proj tile [64 b x 32 cols] into smem
        if (wid >= 8) {
            int t2 = tid - 256;            // 0..255
            int b = t2 >> 2;               // 0..63
            int g = t2 & 3;                // gate
            const float* xp = g_xproj + (size_t)t * BATCH * G4 + (size_t)b * G4
                            + (size_t)g * HID + j * 8;
            float4 v0 = __ldcs((const float4*)xp);
            float4 v1 = __ldcs((const float4*)xp + 1);
            *(float4*)&xs[b][g * 8]     = v0;
            *(float4*)&xs[b][g * 8 + 4] = v1;
        }

        // ---- K-quarter loop: 16 k-steps of m16n8k16, hi/lo split (3 mma per g)
        // A-frag uint4 idx = (s*4 + mt)*64 + lid*2 + part ; per-s stride 256
        const uint4* habase = ((const uint4*)g_hfrag[cb])
                            + ((size_t)(kh * 64 + mt)) * 64 + lid * 2;
        uint4 Ab[4][2];       // ring, fill distance 3
        uint4 Bb[2][4];       // ring, fill distance 1
        float acc[4][4];
#pragma unroll
        for (int g = 0; g < 4; g++)
#pragma unroll
            for (int c = 0; c < 4; c++) acc[g][c] = 0.0f;

#pragma unroll
        for (int p = 0; p < 3; p++) {
            const uint4* ap = habase + (size_t)p * 256;
            Ab[p][0] = __ldcg(ap);
            Ab[p][1] = __ldcg(ap + 1);
        }
#pragma unroll
        for (int g = 0; g < 4; g++) Bb[0][g] = __ldg(wbase + g * 32);

#pragma unroll
        for (int s = 0; s < 16; s++) {
            if (s < 15) {
                const uint4* wp = wbase + (size_t)(s + 1) * 128;
#pragma unroll
                for (int g = 0; g < 4; g++) Bb[(s + 1) & 1][g] = __ldg(wp + g * 32);
            }
            if (s < 13) {
                const uint4* ap = habase + (size_t)(s + 3) * 256;
                Ab[(s + 3) & 3][0] = __ldcg(ap);
                Ab[(s + 3) & 3][1] = __ldcg(ap + 1);
            }
            uint4 A0 = Ab[s & 3][0];
            uint4 A1 = Ab[s & 3][1];
#pragma unroll
            for (int g = 0; g < 4; g++) {
                uint4 B = Bb[s & 1][g];
                MMA_BF16(acc[g], A0, B.x, B.y);
                MMA_BF16(acc[g], A0, B.z, B.w);
                MMA_BF16(acc[g], A1, B.x, B.y);
            }
        }

        // ---- warps kh>=1: partials -> smem
        if (kh >= 1) {
#pragma unroll
            for (int g = 0; g < 4; g++)
#pragma unroll
                for (int c = 0; c < 4; c++)
                    psum[kh - 1][mt][g * 4 + c][lid] = acc[g][c];
        }
        __syncthreads();

        // ---- warps kh==0: reduce + LSTM update
        if (kh == 0) {
#pragma unroll
            for (int q = 0; q < 3; q++)
#pragma unroll
                for (int g = 0; g < 4; g++)
#pragma unroll
                    for (int c = 0; c < 4; c++)
                        acc[g][c] += psum[q][mt][g * 4 + c][lid];

            uint32_t* hb = g_hfrag[nb] + (((sj * 4 + mt) * 32 + lid) * 8);
#pragma unroll
            for (int mh = 0; mh < 2; mh++) {
                int row = r0 + 8 * mh;
                float h2[2];
#pragma unroll
                for (int cbit = 0; cbit < 2; cbit++) {
                    int ci = mh * 2 + cbit;
                    int ul = 2 * tig + cbit;
                    float ig = acc[0][ci] + xs[row][ul]      + bhs[ul];
                    float fg = acc[1][ci] + xs[row][8 + ul]  + bhs[8 + ul];
                    float gg = acc[2][ci] + xs[row][16 + ul] + bhs[16 + ul];
                    float og = acc[3][ci] + xs[row][24 + ul] + bhs[24 + ul];
                    float cn = sigmf(fg) * creg[ci] + sigmf(ig) * tanhf(gg);
                    creg[ci] = cn;
                    h2[cbit] = sigmf(og) * tanhf(cn);
                }
                float hi0 = __bfloat162float(__float2bfloat16(h2[0]));
                float hi1 = __bfloat162float(__float2bfloat16(h2[1]));
                hb[regbase + mh]     = pack_bf16x2(h2[0], h2[1]);
                hb[4 + regbase + mh] = pack_bf16x2(h2[0] - hi0, h2[1] - hi1);
                if (t == SEQ - 1) {
                    *(float2*)(g_hfin + row * HID + j * 8 + 2 * tig) =
                        make_float2(h2[0], h2[1]);
                }
            }
        }
        grid_bar(++barnum);
    }
}

// ===================== head (parallel warp-reduce) — unchanged =====================
__global__ void final_kernel(const float* __restrict__ W1,
                             const float* __restrict__ b1,
                             const float* __restrict__ W2,
                             const float* __restrict__ b2,
                             float* __restrict__ out) {
    __shared__ float hidden[64];
    const int b   = blockIdx.x;
    const int tid = threadIdx.x;
    const int wid = tid >> 5;
    const int lid = tid & 31;
    const float* hrow = g_hfin + b * HID;

#pragma unroll
    for (int q = 0; q < 8; q++) {
        int jj = wid + q * 8;
        const float* wrow = W1 + jj * HID;
        float s = 0.0f;
#pragma unroll 8
        for (int k = lid; k < HID; k += 32) s = fmaf(hrow[k], wrow[k], s);
#pragma unroll
        for (int o = 16; o; o >>= 1) s += __shfl_xor_sync(0xFFFFFFFFu, s, o);
        if (lid == 0) hidden[jj] = fmaxf(s + b1[jj], 0.0f) * W2[jj];
    }
    __syncthreads();
    if (wid == 0) {
        float v = hidden[lid] + hidden[lid + 32];
#pragma unroll
        for (int o = 16; o; o >>= 1) v += __shfl_xor_sync(0xFFFFFFFFu, v, o);
        if (lid == 0) out[b] = v + b2[0];
    }
}

// ===================== launch =====================
extern "C" void kernel_launch(void* const* d_in, const int* in_sizes, int n_in,
                              void* d_out, int out_size) {
    (void)in_sizes; (void)n_in; (void)out_size;
    const int*   x         = (const int*)  d_in[0];
    const float* emb_table = (const float*)d_in[2];
    const float* W_ih      = (const float*)d_in[3];
    const float* b_ih      = (const float*)d_in[4];
    const float* W_hh      = (const float*)d_in[5];
    const float* b_hh      = (const float*)d_in[6];
    const float* W1        = (const float*)d_in[7];
    const float* b1        = (const float*)d_in[8];
    const float* W2        = (const float*)d_in[9];
    const float* b2        = (const float*)d_in[10];
    float* out = (float*)d_out;

    init_kernel<<<1, 32>>>();
    wconv_kernel<<<(4096 * 512 + 255) / 256, 256>>>(W_hh);
    wihconv_kernel<<<(4096 * 256 + 255) / 256, 256>>>(W_ih);
    gather_kernel<<<2048, 256>>>(x, emb_table);
    xproj_mma<<<dim3(256, 16), 256>>>(b_ih);
    lstm_persistent<<<NBLK, 512>>>(b_hh);
    final_kernel<<<BATCH, 256>>>(W1, b1, W2, b2, out);
}